// round 11
// baseline (speedup 1.0000x reference)
#include <cuda_runtime.h>
#include <cuda_fp16.h>
#include <cstdint>

// Problem constants
#define B_DIM   8192
#define IN_DIM  1024
#define OUT_DIM 1024
#define ORD     8              // ORDER+1 powers per input
#define KTOT    (IN_DIM * ORD) // 8192 reduction length

#define BM 128
#define BN 128
#define BK 32                  // 4 inputs * 8 powers per (sub)tile
#define NKT (KTOT / BK)        // 256 base K-tiles
#define NKT2 (NKT / 2)         // 128 supertiles (BK=64)
#define NBM (B_DIM / BM)       // 64
#define NBN (OUT_DIM / BN)     // 8

#define TILE_U4 512            // 8 KB per base tile = 512 uint4
#define STG_BYTES 32768        // stage = A 16KB + B 16KB
#define SMEM_GEMM (3 * STG_BYTES)   // 96 KB, 3 stages

// Precomputed smem-image scratch
//   gA_img[bm][kt] = 8 KB A-tile image (quad-swizzled fp16 powers)   -> 128 MB
//   gB_img[bn][kt] = 8 KB B-tile image (xor-swizzled k-paired half2) ->  16 MB
__device__ __align__(16) uint4 gA_img[(size_t)NBM * NKT * TILE_U4];
__device__ __align__(16) uint4 gB_img[(size_t)NBN * NKT * TILE_U4];

// ---------------------------------------------------------------------------
// Helpers
// ---------------------------------------------------------------------------
__device__ __forceinline__ uint32_t smem_u32(const void* p) {
    uint32_t a;
    asm("{ .reg .u64 t; cvta.to.shared.u64 t, %1; cvt.u32.u64 %0, t; }"
        : "=r"(a) : "l"(p));
    return a;
}
__device__ __forceinline__ uint32_t packh2(float lo, float hi) {
    __half2 h = __floats2half2_rn(lo, hi);
    return *reinterpret_cast<uint32_t*>(&h);
}
__device__ __forceinline__ float tanh_fast(float x) {
    float r;
    asm("tanh.approx.f32 %0, %1;" : "=f"(r) : "f"(x));
    return r;
}
__device__ __forceinline__ void ldsm4(uint32_t* f, uint32_t addr) {
    asm volatile("ldmatrix.sync.aligned.m8n8.x4.shared.b16 {%0,%1,%2,%3}, [%4];"
                 : "=r"(f[0]), "=r"(f[1]), "=r"(f[2]), "=r"(f[3])
                 : "r"(addr) : "memory");
}
__device__ __forceinline__ void mma16816(float* c, const uint32_t* a,
                                         uint32_t b0, uint32_t b1) {
    asm("mma.sync.aligned.m16n8k16.row.col.f32.f16.f16.f32 "
        "{%0,%1,%2,%3}, {%4,%5,%6,%7}, {%8,%9}, {%0,%1,%2,%3};"
        : "+f"(c[0]), "+f"(c[1]), "+f"(c[2]), "+f"(c[3])
        : "r"(a[0]), "r"(a[1]), "r"(a[2]), "r"(a[3]), "r"(b0), "r"(b1));
}
__device__ __forceinline__ void cp16(uint32_t smaddr, const void* g) {
    asm volatile("cp.async.cg.shared.global [%0], [%1], 16;"
                 :: "r"(smaddr), "l"(g) : "memory");
}
__device__ __forceinline__ void cp_commit() {
    asm volatile("cp.async.commit_group;" ::: "memory");
}
__device__ __forceinline__ void cp_wait1() {
    asm volatile("cp.async.wait_group 1;" ::: "memory");
}
__device__ __forceinline__ void cp_wait0() {
    asm volatile("cp.async.wait_group 0;" ::: "memory");
}

// ---------------------------------------------------------------------------
// Prep kernel A (v2, coalesced): one float4 of x = one kt-quad per thread.
// Block = (ktg of 16 kts) x (128 rows); 512 threads: row = tid>>2, u = tid&3.
// iter 0..3: kt = ktg*16 + iter*4 + u -> warp reads contiguous 64B per row.
// Writes 4 swizzled uint4 = 64B contiguous per (row, kt).
//   image uint4 idx (in tile): row*4 + (q ^ ((row>>1)&3))
// ---------------------------------------------------------------------------
__global__ void prep_a_kernel(const float* __restrict__ x,
                              const float* __restrict__ rp) {
    const float r = *rp;
    const int ktg = blockIdx.x;
    const int bm  = blockIdx.y;
    const int tid = threadIdx.x;
    const int row = tid >> 2;
    const int u   = tid & 3;
    const int sw  = (row >> 1) & 3;

    const float4* x4 = reinterpret_cast<const float4*>(x);
    const size_t rowbase = (size_t)(bm * BM + row) * (IN_DIM / 4);

#pragma unroll
    for (int iter = 0; iter < 4; ++iter) {
        const int kt = ktg * 16 + iter * 4 + u;
        const float4 v = x4[rowbase + kt];   // 4 inputs of this kt, this row

        uint4* dst = &gA_img[((size_t)bm * NKT + kt) * TILE_U4 + row * 4];

        const float tq[4] = {
            tanh_fast(v.x * r), tanh_fast(v.y * r),
            tanh_fast(v.z * r), tanh_fast(v.w * r)
        };
#pragma unroll
        for (int q = 0; q < 4; ++q) {
            const float t = tq[q];
            const float t2 = t * t, t3 = t2 * t, t4 = t2 * t2;
            const float t5 = t4 * t, t6 = t3 * t3, t7 = t4 * t3;
            uint4 qv;
            qv.x = packh2(1.f, t);  qv.y = packh2(t2, t3);
            qv.z = packh2(t4, t5);  qv.w = packh2(t6, t7);
            dst[q ^ sw] = qv;
        }
    }
}

// ---------------------------------------------------------------------------
// Prep kernel B: coef -> xor-swizzled k-paired half2 tile image
//   word idx (in tile): q0*128 + (j ^ ((q0&3)<<3)), q0 = k-pair index 0..15
//   content: half2(coef[j][kt*32+2*q0], coef[j][kt*32+2*q0+1])
// ---------------------------------------------------------------------------
__global__ void prep_b_kernel(const float* __restrict__ coef) {
    const int kt = blockIdx.x;
    const int bn = blockIdx.y;
    const int tid = threadIdx.x;
    const int s = tid & 3;        // k-octet slot (8 floats)
    const int j = tid >> 2;       // column 0..127

    const float* cp = &coef[(size_t)(bn * BN + j) * KTOT + kt * BK + s * 8];
    const float4 c0 = *reinterpret_cast<const float4*>(cp);
    const float4 c1 = *reinterpret_cast<const float4*>(cp + 4);

    uint32_t* gw = reinterpret_cast<uint32_t*>(
        &gB_img[((size_t)bn * NKT + kt) * TILE_U4]);
    const int q0 = s * 4;         // q0&3 == u for u = 0..3
    gw[(q0 + 0) * 128 + (j ^ 0)]  = packh2(c0.x, c0.y);
    gw[(q0 + 1) * 128 + (j ^ 8)]  = packh2(c0.z, c0.w);
    gw[(q0 + 2) * 128 + (j ^ 16)] = packh2(c1.x, c1.y);
    gw[(q0 + 3) * 128 + (j ^ 24)] = packh2(c1.z, c1.w);
}

// ---------------------------------------------------------------------------
// GEMM kernel: 3-stage cp.async fp16 m16n8k16 pipeline, BK=64 supertiles.
// 128 threads = 4 warps, 2x2 over the 128x128 block tile, 64x64 per warp.
// Stage layout: [A 16KB (2 base tiles)][B 16KB (2 base tiles)] = 32 KB.
// 96 KB dynamic smem, occupancy 2 (192 KB/SM).
// ---------------------------------------------------------------------------
__global__ __launch_bounds__(128, 2)
void taylor_pipe_kernel(float* __restrict__ out) {
    extern __shared__ __align__(16) uint4 smem[];

    const int tid  = threadIdx.x;
    const int lane = tid & 31;
    const int warp = tid >> 5;
    const int warp_m = warp >> 1;   // 2 warps over M (64 rows each)
    const int warp_n = warp & 1;    // 2 warps over N (64 cols each)
    const int gid = lane >> 2;
    const int tig = lane & 3;

    const int bn = blockIdx.x;
    const int bm = blockIdx.y;

    // per-thread gmem slices: 8 uint4 (128 B) per operand per supertile
    const uint4* gA = &gA_img[(size_t)bm * NKT * TILE_U4 + tid * 8];
    const uint4* gB = &gB_img[(size_t)bn * NKT * TILE_U4 + tid * 8];

    const uint32_t sBase = smem_u32(&smem[0]);
    const uint32_t smA_off = (uint32_t)(tid * 128);
    const uint32_t smB_off = (uint32_t)(16384 + tid * 128);

    // ldmatrix lane geometry (A consumer)
    const int lrow = lane & 15;
    const int lkc  = lane >> 4;
    const int lsw  = (lrow >> 1) & 3;

    float acc[4][8][4];
#pragma unroll
    for (int mt = 0; mt < 4; mt++)
#pragma unroll
        for (int nt = 0; nt < 8; nt++)
#pragma unroll
            for (int c = 0; c < 4; c++) acc[mt][nt][c] = 0.f;

    auto issue = [&](int st, int stage) {
        const uint32_t sa = sBase + stage * STG_BYTES + smA_off;
        const uint32_t sb = sBase + stage * STG_BYTES + smB_off;
        const uint4* ga = gA + (size_t)st * 1024;   // 2 base tiles = 1024 uint4
        const uint4* gb = gB + (size_t)st * 1024;
#pragma unroll
        for (int u = 0; u < 8; u++) {
            cp16(sa + u * 16, ga + u);
            cp16(sb + u * 16, gb + u);
        }
        cp_commit();
    };

    // prologue: fill 2 stages
    issue(0, 0);
    issue(1, 1);

#pragma unroll 1
    for (int st = 0; st < NKT2; ++st) {
        const int stage = st % 3;

        // Steady state: groups {st, st+1} outstanding -> wait_group 1 drains st.
        // Final iteration: only {st} -> wait_group 0 (wait_group 1 would consume
        // a stale tile).
        if (st == NKT2 - 1) cp_wait0(); else cp_wait1();
        __syncthreads();

        // Issue st+2 immediately: its target stage was fully consumed at st-1
        // (protected by the barrier above); copies overlap this tile's mma.
        if (st + 2 < NKT2) issue(st + 2, (st + 2) % 3);

        const uint32_t aBase = sBase + stage * STG_BYTES;
        const uint32_t* sBw = reinterpret_cast<const uint32_t*>(
            reinterpret_cast<const char*>(smem) + stage * STG_BYTES + 16384);

#pragma unroll
        for (int ks = 0; ks < 4; ++ks) {
            const int k   = ks >> 1;   // base tile within supertile
            const int ksl = ks & 1;    // k16-step within base tile

            uint32_t af[4][4];
#pragma unroll
            for (int mt = 0; mt < 4; mt++) {
                const int row_g = warp_m * 64 + mt * 16 + lrow;
                const int qp = (ksl * 2 + lkc) ^ lsw;
                ldsm4(af[mt], aBase + (uint32_t)(k * 8192 + row_g * 64 + qp * 16));
            }
#pragma unroll
            for (int nt = 0; nt < 8; nt++) {
                const int col = warp_n * 64 + nt * 8 + gid;
                const int q0 = ksl * 8 + tig;
                const int widx = k * 2048 + q0 * 128 + (col ^ (tig << 3));
                const uint32_t b0 = sBw[widx];
                const uint32_t b1 = sBw[widx + 4 * 128];
#pragma unroll
                for (int mt = 0; mt < 4; mt++)
                    mma16816(acc[mt][nt], af[mt], b0, b1);
            }
        }
    }

    // ---- epilogue: float2 stores ----
    const int bm0 = bm * BM, bn0 = bn * BN;
#pragma unroll
    for (int mt = 0; mt < 4; mt++) {
        const int row = bm0 + warp_m * 64 + mt * 16 + gid;
#pragma unroll
        for (int nt = 0; nt < 8; nt++) {
            const int col = bn0 + warp_n * 64 + nt * 8 + tig * 2;
            *reinterpret_cast<float2*>(&out[(size_t)row * OUT_DIM + col]) =
                make_float2(acc[mt][nt][0], acc[mt][nt][1]);
            *reinterpret_cast<float2*>(&out[(size_t)(row + 8) * OUT_DIM + col]) =
                make_float2(acc[mt][nt][2], acc[mt][nt][3]);
        }
    }
}

// ---------------------------------------------------------------------------
// Launch
// ---------------------------------------------------------------------------
extern "C" void kernel_launch(void* const* d_in, const int* in_sizes, int n_in,
                              void* d_out, int out_size) {
    const float* x    = (const float*)d_in[0];   // [8192, 1024] f32
    const float* rng  = (const float*)d_in[1];   // scalar f32
    const float* coef = (const float*)d_in[2];   // [1024, 1024, 8] f32
    float* out        = (float*)d_out;           // [8192, 1024] f32

    (void)in_sizes; (void)n_in; (void)out_size;

    // 1) prep A-tile images (tanh + powers, fp16, swizzled) — coalesced v2
    {
        dim3 grid(NKT / 16, NBM);   // (16, 64)
        prep_a_kernel<<<grid, 512>>>(x, rng);
    }
    // 2) prep B-tile images (coef -> fp16 k-paired, swizzled)
    {
        dim3 grid(NKT, NBN);   // (256, 8)
        prep_b_kernel<<<grid, 512>>>(coef);
    }
    // 3) pipelined fp16 tensor-core GEMM (BK=64 supertiles, 96 KB dyn smem)
    {
        cudaFuncSetAttribute(taylor_pipe_kernel,
                             cudaFuncAttributeMaxDynamicSharedMemorySize,
                             SMEM_GEMM);
        dim3 grid(NBN, NBM);   // (8, 64)
        taylor_pipe_kernel<<<grid, 128, SMEM_GEMM>>>(out);
    }
}

// round 12
// speedup vs baseline: 1.7158x; 1.7158x over previous
#include <cuda_runtime.h>
#include <cuda_fp16.h>
#include <cstdint>

// Problem constants
#define B_DIM   8192
#define IN_DIM  1024
#define OUT_DIM 1024
#define ORD     8              // ORDER+1 powers per input
#define KTOT    (IN_DIM * ORD) // 8192 reduction length

#define BM 128
#define BN 128
#define BK 32                  // 4 inputs * 8 powers per K-tile
#define NKT (KTOT / BK)        // 256 K-tiles
#define NBM (B_DIM / BM)       // 64
#define NBN (OUT_DIM / BN)     // 8

#define STAGES 4
#define TILE_U4 512            // 8 KB per operand tile = 512 uint4
#define STG_BYTES 16384        // stage = A 8KB + B 8KB
#define SMEM_GEMM (STAGES * STG_BYTES)   // 64 KB dynamic

// Precomputed smem-image scratch
//   gA_img[bm][kt] = 8 KB A-tile image (quad-swizzled fp16 powers)   -> 128 MB
//   gB_img[bn][kt] = 8 KB B-tile image (xor-swizzled k-paired half2) ->  16 MB
__device__ __align__(16) uint4 gA_img[(size_t)NBM * NKT * TILE_U4];
__device__ __align__(16) uint4 gB_img[(size_t)NBN * NKT * TILE_U4];

// ---------------------------------------------------------------------------
// Helpers
// ---------------------------------------------------------------------------
__device__ __forceinline__ uint32_t smem_u32(const void* p) {
    uint32_t a;
    asm("{ .reg .u64 t; cvta.to.shared.u64 t, %1; cvt.u32.u64 %0, t; }"
        : "=r"(a) : "l"(p));
    return a;
}
__device__ __forceinline__ uint32_t packh2(float lo, float hi) {
    __half2 h = __floats2half2_rn(lo, hi);
    return *reinterpret_cast<uint32_t*>(&h);
}
__device__ __forceinline__ float tanh_fast(float x) {
    float r;
    asm("tanh.approx.f32 %0, %1;" : "=f"(r) : "f"(x));
    return r;
}
__device__ __forceinline__ void ldsm4(uint32_t* f, uint32_t addr) {
    asm volatile("ldmatrix.sync.aligned.m8n8.x4.shared.b16 {%0,%1,%2,%3}, [%4];"
                 : "=r"(f[0]), "=r"(f[1]), "=r"(f[2]), "=r"(f[3])
                 : "r"(addr) : "memory");
}
__device__ __forceinline__ void mma16816(float* c, const uint32_t* a,
                                         uint32_t b0, uint32_t b1) {
    asm("mma.sync.aligned.m16n8k16.row.col.f32.f16.f16.f32 "
        "{%0,%1,%2,%3}, {%4,%5,%6,%7}, {%8,%9}, {%0,%1,%2,%3};"
        : "+f"(c[0]), "+f"(c[1]), "+f"(c[2]), "+f"(c[3])
        : "r"(a[0]), "r"(a[1]), "r"(a[2]), "r"(a[3]), "r"(b0), "r"(b1));
}
__device__ __forceinline__ void cp16(uint32_t smaddr, const void* g) {
    asm volatile("cp.async.cg.shared.global [%0], [%1], 16;"
                 :: "r"(smaddr), "l"(g) : "memory");
}
__device__ __forceinline__ void cp_commit() {
    asm volatile("cp.async.commit_group;" ::: "memory");
}
__device__ __forceinline__ void cp_wait2() {
    asm volatile("cp.async.wait_group 2;" ::: "memory");
}
__device__ __forceinline__ void cp_wait1() {
    asm volatile("cp.async.wait_group 1;" ::: "memory");
}
__device__ __forceinline__ void cp_wait0() {
    asm volatile("cp.async.wait_group 0;" ::: "memory");
}

// ---------------------------------------------------------------------------
// Prep kernel A (R9 version): tanh + powers -> quad-swizzled fp16 tile image
//   image uint4 idx (in tile): row*4 + (q ^ ((row>>1)&3))
//   content: half2 pairs {1,t},{t2,t3},{t4,t5},{t6,t7} of t = tanh(x*r)
// ---------------------------------------------------------------------------
__global__ void prep_a_kernel(const float* __restrict__ x,
                              const float* __restrict__ rp) {
    const float r = *rp;
    const int kt = blockIdx.x;
    const int bm = blockIdx.y;
    const int tid = threadIdx.x;
    const int row = tid >> 2;
    const int q   = tid & 3;

    const float xv = x[(size_t)(bm * BM + row) * IN_DIM + kt * 4 + q];
    const float t  = tanh_fast(xv * r);
    const float t2 = t * t, t3 = t2 * t, t4 = t2 * t2;
    const float t5 = t4 * t, t6 = t3 * t3, t7 = t4 * t3;

    uint4 qv;
    qv.x = packh2(1.f, t);  qv.y = packh2(t2, t3);
    qv.z = packh2(t4, t5);  qv.w = packh2(t6, t7);

    gA_img[((size_t)bm * NKT + kt) * TILE_U4 + row * 4 + (q ^ ((row >> 1) & 3))] = qv;
}

// ---------------------------------------------------------------------------
// Prep kernel B: coef -> xor-swizzled k-paired half2 tile image
//   word idx (in tile): q0*128 + (j ^ ((q0&3)<<3)), q0 = k-pair index 0..15
//   content: half2(coef[j][kt*32+2*q0], coef[j][kt*32+2*q0+1])
// ---------------------------------------------------------------------------
__global__ void prep_b_kernel(const float* __restrict__ coef) {
    const int kt = blockIdx.x;
    const int bn = blockIdx.y;
    const int tid = threadIdx.x;
    const int s = tid & 3;        // k-octet slot (8 floats)
    const int j = tid >> 2;       // column 0..127

    const float* cp = &coef[(size_t)(bn * BN + j) * KTOT + kt * BK + s * 8];
    const float4 c0 = *reinterpret_cast<const float4*>(cp);
    const float4 c1 = *reinterpret_cast<const float4*>(cp + 4);

    uint32_t* gw = reinterpret_cast<uint32_t*>(
        &gB_img[((size_t)bn * NKT + kt) * TILE_U4]);
    const int q0 = s * 4;         // q0&3 == u for u = 0..3
    gw[(q0 + 0) * 128 + (j ^ 0)]  = packh2(c0.x, c0.y);
    gw[(q0 + 1) * 128 + (j ^ 8)]  = packh2(c0.z, c0.w);
    gw[(q0 + 2) * 128 + (j ^ 16)] = packh2(c1.x, c1.y);
    gw[(q0 + 3) * 128 + (j ^ 24)] = packh2(c1.z, c1.w);
}

// ---------------------------------------------------------------------------
// GEMM kernel: 4-stage cp.async fp16 m16n8k16 pipeline (R9 layout, deeper).
// 128 threads = 4 warps, 2x2 over the 128x128 block tile, 64x64 per warp.
// Stage layout: [A 8KB][B 8KB] = 16 KB; 4 stages = 64 KB dynamic smem.
// Copy mapping: thread writes 2x16B at tid*32 -> fully contiguous (R9-validated).
// ---------------------------------------------------------------------------
__global__ __launch_bounds__(128, 2)
void taylor_pipe_kernel(float* __restrict__ out) {
    extern __shared__ __align__(16) uint4 smem[];

    const int tid  = threadIdx.x;
    const int lane = tid & 31;
    const int warp = tid >> 5;
    const int warp_m = warp >> 1;   // 2 warps over M (64 rows each)
    const int warp_n = warp & 1;    // 2 warps over N (64 cols each)
    const int gid = lane >> 2;
    const int tig = lane & 3;

    const int bn = blockIdx.x;
    const int bm = blockIdx.y;

    const uint4* gA = &gA_img[(size_t)bm * NKT * TILE_U4 + tid * 4];
    const uint4* gB = &gB_img[(size_t)bn * NKT * TILE_U4 + tid * 4];

    const uint32_t sBase = smem_u32(&smem[0]);
    // per-thread smem targets within a stage (contiguous across threads)
    const uint32_t smA_off = (uint32_t)(tid * 64);
    const uint32_t smB_off = (uint32_t)(8192 + tid * 64);

    // ldmatrix lane geometry (A consumer)
    const int lrow = lane & 15;
    const int lkc  = lane >> 4;
    const int lsw  = (lrow >> 1) & 3;

    float acc[4][8][4];
#pragma unroll
    for (int mt = 0; mt < 4; mt++)
#pragma unroll
        for (int nt = 0; nt < 8; nt++)
#pragma unroll
            for (int c = 0; c < 4; c++) acc[mt][nt][c] = 0.f;

    auto issue = [&](int kt, int stage) {
        const uint32_t sa = sBase + stage * STG_BYTES + smA_off;
        const uint32_t sb = sBase + stage * STG_BYTES + smB_off;
        const uint4* ga = gA + (size_t)kt * TILE_U4;
        const uint4* gb = gB + (size_t)kt * TILE_U4;
#pragma unroll
        for (int u = 0; u < 4; u++) {
            cp16(sa + u * 16, ga + u);
            cp16(sb + u * 16, gb + u);
        }
        cp_commit();
    };

    // prologue: fill 3 stages
    issue(0, 0);
    issue(1, 1);
    issue(2, 2);

#pragma unroll 1
    for (int kt = 0; kt < NKT; ++kt) {
        const int stage = kt & 3;

        // Drain the group carrying tile kt. Steady state: groups
        // {kt, kt+1, kt+2} outstanding -> wait_group 2. Tail: fewer groups
        // remain, so tighten the wait (wait_group 2 would otherwise return
        // without draining kt -> stale-tile consumption, the R7 bug class).
        if (kt < NKT - 2)      cp_wait2();
        else if (kt == NKT - 2) cp_wait1();
        else                    cp_wait0();
        __syncthreads();

        // Issue kt+3 now: its target stage (kt-1 mod 4) was consumed in
        // iteration kt-1; the barrier above makes that consumption global.
        // Copies overlap this tile's mma phase.
        if (kt + 3 < NKT) issue(kt + 3, (kt + 3) & 3);

        const uint32_t aBase = sBase + stage * STG_BYTES;
        const uint32_t* sBw = reinterpret_cast<const uint32_t*>(
            reinterpret_cast<const char*>(smem) + stage * STG_BYTES + 8192);

#pragma unroll
        for (int ks = 0; ks < 2; ++ks) {
            uint32_t af[4][4];
#pragma unroll
            for (int mt = 0; mt < 4; mt++) {
                const int row_g = warp_m * 64 + mt * 16 + lrow;
                const int qp = (ks * 2 + lkc) ^ lsw;
                ldsm4(af[mt], aBase + (uint32_t)(row_g * 64 + qp * 16));
            }
#pragma unroll
            for (int nt = 0; nt < 8; nt++) {
                const int col = warp_n * 64 + nt * 8 + gid;
                const int q0 = ks * 8 + tig;
                const int widx = q0 * 128 + (col ^ (tig << 3));
                const uint32_t b0 = sBw[widx];
                const uint32_t b1 = sBw[widx + 4 * 128];
#pragma unroll
                for (int mt = 0; mt < 4; mt++)
                    mma16816(acc[mt][nt], af[mt], b0, b1);
            }
        }
    }

    // ---- epilogue: float2 stores ----
    const int bm0 = bm * BM, bn0 = bn * BN;
#pragma unroll
    for (int mt = 0; mt < 4; mt++) {
        const int row = bm0 + warp_m * 64 + mt * 16 + gid;
#pragma unroll
        for (int nt = 0; nt < 8; nt++) {
            const int col = bn0 + warp_n * 64 + nt * 8 + tig * 2;
            *reinterpret_cast<float2*>(&out[(size_t)row * OUT_DIM + col]) =
                make_float2(acc[mt][nt][0], acc[mt][nt][1]);
            *reinterpret_cast<float2*>(&out[(size_t)(row + 8) * OUT_DIM + col]) =
                make_float2(acc[mt][nt][2], acc[mt][nt][3]);
        }
    }
}

// ---------------------------------------------------------------------------
// Launch
// ---------------------------------------------------------------------------
extern "C" void kernel_launch(void* const* d_in, const int* in_sizes, int n_in,
                              void* d_out, int out_size) {
    const float* x    = (const float*)d_in[0];   // [8192, 1024] f32
    const float* rng  = (const float*)d_in[1];   // scalar f32
    const float* coef = (const float*)d_in[2];   // [1024, 1024, 8] f32
    float* out        = (float*)d_out;           // [8192, 1024] f32

    (void)in_sizes; (void)n_in; (void)out_size;

    // 1) prep A-tile images (tanh + powers, fp16, swizzled)
    {
        dim3 grid(NKT, NBM);   // (256, 64)
        prep_a_kernel<<<grid, 512>>>(x, rng);
    }
    // 2) prep B-tile images (coef -> fp16 k-paired, swizzled)
    {
        dim3 grid(NKT, NBN);   // (256, 8)
        prep_b_kernel<<<grid, 512>>>(coef);
    }
    // 3) pipelined fp16 tensor-core GEMM (4 stages, 64 KB dyn smem)
    {
        cudaFuncSetAttribute(taylor_pipe_kernel,
                             cudaFuncAttributeMaxDynamicSharedMemorySize,
                             SMEM_GEMM);
        dim3 grid(NBN, NBM);   // (8, 64)
        taylor_pipe_kernel<<<grid, 128, SMEM_GEMM>>>(out);
    }
}